// round 7
// baseline (speedup 1.0000x reference)
#include <cuda_runtime.h>
#include <cuda_fp16.h>
#include <cstdint>

#define NQ      8
#define DIM     256
#define MT      128              // batch rows per CTA
#define NCHUNK  2                // N processed in 2 chunks of 256 cols
#define SLICES  12               // K slices per chunk (768 / 64)
#define GSLICES 24               // total slices
#define BSTRIDE 144              // B smem row: 128 B data + 16 B pad
#define BROWS   256              // n-rows per slice
#define BSLICE  (BROWS * BSTRIDE)   // 36864 B per slice
#define ASTRIDE 1040             // A smem row: 1024 B data + 16 B pad
#define ABYTES  (128 * ASTRIDE)  // 133120
#define NTHREADS 544             // 16 MMA warps + 1 producer warp
#define SMEM_TOTAL (ABYTES + 2 * BSLICE + 128)   // + mbarrier block

// W slice images, laid out exactly as the smem B buffer (padded [n][k] rows).
// Per N-chunk (256 cols): s0-3 = Whi(j-block 0-3), s4-7 = Whi again (ylo pass),
// s8-11 = Wlo.  Linear slice index = chunk*12 + s.
__device__ __align__(128) unsigned char d_B[NCHUNK * SLICES * BSLICE];  // 884736 B

// ---------------- helpers ----------------
__device__ __forceinline__ uint32_t smem_u32(const void* p) {
    uint32_t a;
    asm("{ .reg .u64 t; cvta.to.shared.u64 t, %1; cvt.u32.u64 %0, t; }" : "=r"(a) : "l"(p));
    return a;
}

#define MBAR_INIT(a, n)  asm volatile("mbarrier.init.shared.b64 [%0], %1;" :: "r"(a), "r"((uint32_t)(n)) : "memory")
#define MBAR_EXPECT(a, n) asm volatile("mbarrier.arrive.expect_tx.shared.b64 _, [%0], %1;" :: "r"(a), "r"((uint32_t)(n)) : "memory")
#define MBAR_ARRIVE(a)   asm volatile("mbarrier.arrive.release.cta.shared::cta.b64 _, [%0];" :: "r"(a) : "memory")
#define MBAR_WAIT(a, ph) do {                                                        \
    uint32_t _m = (a), _p = (ph), _d;                                                \
    asm volatile("{ .reg .pred p; mbarrier.try_wait.parity.acquire.cta.shared::cta.b64 p, [%1], %2; selp.b32 %0,1,0,p; }" \
                 : "=r"(_d) : "r"(_m), "r"(_p) : "memory");                          \
    if (!_d) {                                                                       \
        asm volatile("{ .reg .pred P1; W%=: mbarrier.try_wait.parity.acquire.cta.shared::cta.b64 P1, [%0], %1, 0x989680;" \
                     " @P1 bra.uni D%=; bra.uni W%=; D%=: }" :: "r"(_m), "r"(_p) : "memory"); \
    }                                                                                \
} while (0)

__device__ __forceinline__ void bulk_g2s(uint32_t dst, const void* src, uint32_t bytes, uint32_t mbar) {
    asm volatile("cp.async.bulk.shared::cluster.global.mbarrier::complete_tx::bytes [%0], [%1], %2, [%3];"
        :: "r"(dst), "l"(src), "r"(bytes), "r"(mbar) : "memory");
}

#define LDSM4(r, addr) \
    asm volatile("ldmatrix.sync.aligned.m8n8.x4.shared.b16 {%0,%1,%2,%3}, [%4];" \
        : "=r"((r)[0]), "=r"((r)[1]), "=r"((r)[2]), "=r"((r)[3]) : "r"(addr))

#define MMA16816(c, a, bb0, bb1) \
    asm volatile("mma.sync.aligned.m16n8k16.row.col.f32.f16.f16.f32 " \
        "{%0,%1,%2,%3}, {%4,%5,%6,%7}, {%8,%9}, {%0,%1,%2,%3};" \
        : "+f"((c)[0]), "+f"((c)[1]), "+f"((c)[2]), "+f"((c)[3]) \
        : "r"((a)[0]), "r"((a)[1]), "r"((a)[2]), "r"((a)[3]), "r"(bb0), "r"(bb1))

// ============================================================
// Kernel A: build U column j; emit fp16 hi/lo W slice images.
// ============================================================
__device__ __forceinline__ float2 cmul(float2 a, float2 b) {
    return make_float2(a.x * b.x - a.y * b.y, a.x * b.y + a.y * b.x);
}
__device__ __forceinline__ float2 cadd(float2 a, float2 b) {
    return make_float2(a.x + b.x, a.y + b.y);
}

__global__ void build_U_kernel(const float* __restrict__ w) {
    __shared__ float2 st[DIM];
    const int j = blockIdx.x;
    const int t = threadIdx.x;  // 0..127

    st[t]       = make_float2(t == j ? 1.f : 0.f, 0.f);
    st[t + 128] = make_float2((t + 128) == j ? 1.f : 0.f, 0.f);
    __syncthreads();

    for (int l = 0; l < 6; ++l) {
        const int r = l % (NQ - 1) + 1;
        for (int q = 0; q < NQ; ++q) {
            const float phi = w[(l * NQ + q) * 3 + 0];
            const float th  = w[(l * NQ + q) * 3 + 1];
            const float om  = w[(l * NQ + q) * 3 + 2];
            const float ct = cosf(0.5f * th), sth = sinf(0.5f * th);
            const float a  = 0.5f * (phi + om), bb = 0.5f * (phi - om);
            const float ca = cosf(a),  sa = sinf(a);
            const float cb = cosf(bb), sb = sinf(bb);
            const float2 u00 = make_float2( ca * ct, -sa * ct);
            const float2 u01 = make_float2(-cb * sth, -sb * sth);
            const float2 u10 = make_float2( cb * sth, -sb * sth);
            const float2 u11 = make_float2( ca * ct,  sa * ct);

            const int b    = 7 - q;
            const int mask = 1 << b;
            const int low  = t & (mask - 1);
            const int k0   = ((t >> b) << (b + 1)) | low;
            const int k1   = k0 | mask;
            const float2 a0 = st[k0], a1 = st[k1];
            st[k0] = cadd(cmul(u00, a0), cmul(u01, a1));
            st[k1] = cadd(cmul(u10, a0), cmul(u11, a1));
            __syncthreads();
        }
        for (int q = 0; q < NQ; ++q) {
            const int tq = (q + r) % NQ;
            const int cb = 7 - q;
            const int tb = 7 - tq;
            if (t < 64) {
                const int plo = cb < tb ? cb : tb;
                const int phi_ = cb < tb ? tb : cb;
                const int low  = t & ((1 << plo) - 1);
                const int mid  = (t >> plo) & ((1 << (phi_ - plo - 1)) - 1);
                const int high = t >> (phi_ - 1);
                const int k0   = low | (mid << (plo + 1)) | (high << (phi_ + 1));
                const int k    = k0 | (1 << cb);
                const int p    = k  | (1 << tb);
                const float2 tmp = st[k];
                st[k] = st[p];
                st[p] = tmp;
            }
            __syncthreads();
        }
    }

    // Emit B slice images for this j (st[k] = U[k][j]).
    //   even popc(j): (w0,w1) = ( Re,  Im);  odd: (w0,w1) = ( Im, -Re)
    const bool odd = (__popc(j) & 1) != 0;
    const int s0 = j >> 6;
    const int koff = (j & 63) * 2;
#pragma unroll
    for (int h = 0; h < 2; ++h) {
        const int kst = t + h * 128;
        const float2 u = st[kst];
        const float W0 = odd ?  u.y : u.x;
        const float W1 = odd ? -u.x : u.y;
#pragma unroll
        for (int comp = 0; comp < 2; ++comp) {
            const float val = comp ? W1 : W0;
            const __half hi = __float2half_rn(val);
            const __half lo = __float2half_rn(val - __half2float(hi));
            const int c = 2 * kst + comp;
            const int chunk = c >> 8, n = c & 255;   // 256 cols per chunk
            const size_t rowbase = (size_t)(chunk * SLICES) * BROWS;
            *(__half*)(d_B + ((rowbase + (size_t)(s0     ) * BROWS + n) * BSTRIDE + koff)) = hi;
            *(__half*)(d_B + ((rowbase + (size_t)(4 + s0 ) * BROWS + n) * BSTRIDE + koff)) = hi;
            *(__half*)(d_B + ((rowbase + (size_t)(8 + s0 ) * BROWS + n) * BSTRIDE + koff)) = lo;
        }
    }
}

// ============================================================
// Kernel B: warp-specialized fp16 mma.sync GEMM.
// 544 threads = 16 MMA warps (4Mx4N, warp tile 32x64) + 1 producer.
// Pointwise mbarrier pipeline: full[2] (tx) + empty[2] (count 512).
// ============================================================
__global__ void __launch_bounds__(NTHREADS, 1) sim_kernel(const float* __restrict__ inp,
                                                          float* __restrict__ out) {
    extern __shared__ __align__(1024) unsigned char smem[];
    const uint32_t sb = smem_u32(smem);
    const uint32_t Ab = sb;
    const uint32_t Bb = sb + ABYTES;
    const uint32_t MB = sb + ABYTES + 2 * BSLICE;   // full0, full1, empty0, empty1
    const int tid = threadIdx.x;
    const int lane = tid & 31, warp = tid >> 5;
    const int wm = warp & 3, wn = warp >> 2;        // 4 x 4 warp grid (warps 0-15)
    const int b0 = blockIdx.x * MT;

    if (tid == 0) {
        MBAR_INIT(MB + 0, 1);  MBAR_INIT(MB + 8, 1);      // full (tx-based)
        MBAR_INIT(MB + 16, 512); MBAR_INIT(MB + 24, 512); // empty
    }
    __syncthreads();

    // consumers pre-arrive on both empties so producer's first waits pass
    if (tid < 512) { MBAR_ARRIVE(MB + 16); MBAR_ARRIVE(MB + 24); }

    // ---- A build: y hi (k 0-255) and lo (k 256-511), fp16; 4 threads/row ----
    if (tid < 512) {
        const int row = tid >> 2, seg = tid & 3;
        const float4 x0 = *(const float4*)(inp + (size_t)(b0 + row) * 8);
        const float4 x1 = *(const float4*)(inp + (size_t)(b0 + row) * 8 + 4);
        const float xs[8] = {x0.x, x0.y, x0.z, x0.w, x1.x, x1.y, x1.z, x1.w};
        float fc[8], fs[8];
#pragma unroll
        for (int q = 0; q < 8; ++q) sincosf(0.5f * xs[q], &fs[q], &fc[q]);
        float ph[16], pl[16];
#pragma unroll
        for (int i = 0; i < 16; ++i) {
            ph[i] = ((i & 8) ? fs[0] : fc[0]) * ((i & 4) ? fs[1] : fc[1]) *
                    ((i & 2) ? fs[2] : fc[2]) * ((i & 1) ? fs[3] : fc[3]);
            pl[i] = ((i & 8) ? fs[4] : fc[4]) * ((i & 4) ? fs[5] : fc[5]) *
                    ((i & 2) ? fs[6] : fc[6]) * ((i & 1) ? fs[7] : fc[7]);
        }
        unsigned char* arow = smem + (size_t)row * ASTRIDE;
#pragma unroll 4
        for (int i = 0; i < 64; i += 2) {
            const int jj = seg * 64 + i;
            float y0 = ph[jj >> 4] * pl[jj & 15];
            float y1 = ph[(jj + 1) >> 4] * pl[(jj + 1) & 15];
            if ((__popc(jj) & 3) >= 2)       y0 = -y0;
            if ((__popc(jj + 1) & 3) >= 2)   y1 = -y1;
            const __half h0 = __float2half_rn(y0), h1 = __float2half_rn(y1);
            const __half l0 = __float2half_rn(y0 - __half2float(h0));
            const __half l1 = __float2half_rn(y1 - __half2float(h1));
            __half2 hp; hp.x = h0; hp.y = h1;
            __half2 lp; lp.x = l0; lp.y = l1;
            *(__half2*)(arow + jj * 2)       = hp;
            *(__half2*)(arow + 512 + jj * 2) = lp;
        }
    }
    __syncthreads();   // A ready; empties pre-armed

    float z[4][8];
#pragma unroll
    for (int zr = 0; zr < 4; ++zr)
#pragma unroll
        for (int i = 0; i < 8; ++i) z[zr][i] = 0.f;

    if (tid >= 512) {
        // ---------------- producer warp ----------------
        if (tid == 512) {
#pragma unroll 1
            for (int gs = 0; gs < GSLICES; ++gs) {
                const uint32_t buf = (uint32_t)(gs & 1);
                const uint32_t par = (uint32_t)((gs >> 1) & 1);
                MBAR_WAIT(MB + 16 + buf * 8, par);       // buffer free
                MBAR_EXPECT(MB + buf * 8, BSLICE);
                bulk_g2s(Bb + buf * BSLICE, d_B + (size_t)gs * BSLICE, BSLICE, MB + buf * 8);
            }
        }
    } else {
        // ---------------- 16 consumer warps ----------------
        const uint32_t aoff = (uint32_t)((wm * 32 + (lane & 7) + ((lane >> 3) & 1) * 8) * ASTRIDE)
                            + ((lane >> 4) & 1) * 16;
        const uint32_t boff = (uint32_t)((wn * 64 + (lane & 7) + ((lane >> 4) & 1) * 8) * BSTRIDE)
                            + ((lane >> 3) & 1) * 16;
        int gs = 0;
        for (int chunk = 0; chunk < NCHUNK; ++chunk) {
            float acc[2][8][4];
#pragma unroll
            for (int mf = 0; mf < 2; ++mf)
#pragma unroll
                for (int nf = 0; nf < 8; ++nf)
#pragma unroll
                    for (int c = 0; c < 4; ++c) acc[mf][nf][c] = 0.f;

#pragma unroll 1
            for (int s = 0; s < SLICES; ++s, ++gs) {
                const uint32_t buf = (uint32_t)(gs & 1);
                const uint32_t par = (uint32_t)((gs >> 1) & 1);
                MBAR_WAIT(MB + buf * 8, par);            // buffer full
                const uint32_t bbase = Bb + buf * BSLICE + boff;
                // A k start (bytes): s 0-3 -> yhi, 4-7 -> ylo, 8-11 -> yhi
                const uint32_t ka2 = 2u * ((s < 4) ? (uint32_t)s * 64u
                                      : (s < 8) ? 256u + (uint32_t)(s - 4) * 64u
                                                : (uint32_t)(s - 8) * 64u);
                const uint32_t abase = Ab + aoff + ka2;
#pragma unroll
                for (int t4 = 0; t4 < 4; ++t4) {
                    uint32_t a[2][4], br[4][4];
#pragma unroll
                    for (int mf = 0; mf < 2; ++mf)
                        LDSM4(a[mf], abase + (uint32_t)mf * (16u * ASTRIDE) + (uint32_t)t4 * 32u);
#pragma unroll
                    for (int nb = 0; nb < 4; ++nb)
                        LDSM4(br[nb], bbase + (uint32_t)nb * (16u * BSTRIDE) + (uint32_t)t4 * 32u);
#pragma unroll
                    for (int mf = 0; mf < 2; ++mf)
#pragma unroll
                        for (int nf = 0; nf < 8; ++nf)
                            MMA16816(acc[mf][nf], a[mf], br[nf >> 1][(nf & 1) * 2],
                                     br[nf >> 1][(nf & 1) * 2 + 1]);
                }
                MBAR_ARRIVE(MB + 16 + buf * 8);          // done reading buffer
            }

            // chunk epilogue: p = Re^2 + Im^2 (in-lane), fold signs into z
#pragma unroll
            for (int nf = 0; nf < 8; ++nf) {
                const int kst = chunk * 128 + wn * 32 + nf * 4 + (lane & 3);
                float sg[8];
#pragma unroll
                for (int i = 0; i < 8; ++i)
                    sg[i] = ((kst >> (7 - i)) & 1) ? -1.f : 1.f;
#pragma unroll
                for (int mf = 0; mf < 2; ++mf) {
                    const float p0 = acc[mf][nf][0] * acc[mf][nf][0] + acc[mf][nf][1] * acc[mf][nf][1];
                    const float p1 = acc[mf][nf][2] * acc[mf][nf][2] + acc[mf][nf][3] * acc[mf][nf][3];
#pragma unroll
                    for (int i = 0; i < 8; ++i) {
                        z[mf * 2][i]     = fmaf(sg[i], p0, z[mf * 2][i]);
                        z[mf * 2 + 1][i] = fmaf(sg[i], p1, z[mf * 2 + 1][i]);
                    }
                }
            }
        }
    }

    __syncthreads();   // all A/B reads done; reuse smem for z reduction
    if (warp < 16) {
        float* zbuf = (float*)smem;
        const int base = (warp * 32 + lane) * 32;
#pragma unroll
        for (int zr = 0; zr < 4; ++zr)
#pragma unroll
            for (int i = 0; i < 8; ++i)
                zbuf[base + zr * 8 + i] = z[zr][i];
    }
    __syncthreads();
    if (tid < 512) {
        const float* zbuf = (const float*)smem;
        const int r = tid >> 2, o = tid & 3;        // row, output pair
        const int wmr = r >> 5, tt = r & 31;
        const int mf = tt >> 4, hh = (tt >> 3) & 1, lhi = tt & 7;
        const int zr = mf * 2 + hh;
        float2 sum = make_float2(0.f, 0.f);
#pragma unroll
        for (int wnn = 0; wnn < 4; ++wnn)
#pragma unroll
            for (int ll = 0; ll < 4; ++ll) {
                const float2 v = *(const float2*)&zbuf[((wnn * 4 + wmr) * 32 + lhi * 4 + ll) * 32
                                                       + zr * 8 + o * 2];
                sum.x += v.x; sum.y += v.y;
            }
        *(float2*)(out + (size_t)(b0 + r) * 8 + o * 2) = sum;
    }
}

// ============================================================
extern "C" void kernel_launch(void* const* d_in, const int* in_sizes, int n_in,
                              void* d_out, int out_size) {
    const float* inputs  = (const float*)d_in[0];  // (65536, 8) float32
    const float* weights = (const float*)d_in[1];  // (6, 8, 3) float32
    float* out = (float*)d_out;                    // (65536, 8) float32

    const int B = in_sizes[0] / NQ;

    static int configured = 0;
    if (!configured) {
        cudaFuncSetAttribute(sim_kernel, cudaFuncAttributeMaxDynamicSharedMemorySize, SMEM_TOTAL);
        configured = 1;
    }

    build_U_kernel<<<DIM, 128>>>(weights);
    sim_kernel<<<B / MT, NTHREADS, SMEM_TOTAL>>>(inputs, out);
}

// round 8
// speedup vs baseline: 1.5079x; 1.5079x over previous
#include <cuda_runtime.h>
#include <cuda_fp16.h>
#include <cstdint>

#define NQ      8
#define DIM     256
#define MT      128              // batch rows per CTA
#define NCHUNK  4                // N processed in 4 chunks of 128 cols
#define CSLICES 4                // B slices per chunk (K=256 of Whi)
#define GSLICES 16               // total B slices
#define BSTRIDE 144              // B smem row: 128 B data + 16 B pad
#define BROWS   128              // n-rows per slice
#define BSLICE  (BROWS * BSTRIDE)   // 18432 B per slice
#define ASTRIDE 1040             // A smem row: 1024 B data + 16 B pad
#define ABYTES  (128 * ASTRIDE)  // 133120
#define SMEM_TOTAL (ABYTES + 2 * BSLICE + 64)   // 170112

// Whi slice images, laid out exactly as the smem B buffer (padded [n][k] rows).
// Slice gs = chunk*4 + jblock: rows = N cols [chunk*128, chunk*128+128),
// k cols = j in [jblock*64, jblock*64+64).
__device__ __align__(128) unsigned char d_B[GSLICES * BSLICE];  // 294912 B

// ---------------- helpers ----------------
__device__ __forceinline__ uint32_t smem_u32(const void* p) {
    uint32_t a;
    asm("{ .reg .u64 t; cvta.to.shared.u64 t, %1; cvt.u32.u64 %0, t; }" : "=r"(a) : "l"(p));
    return a;
}

#define MBAR_INIT(a, n)  asm volatile("mbarrier.init.shared.b64 [%0], %1;" :: "r"(a), "r"((uint32_t)(n)) : "memory")
#define MBAR_EXPECT(a, n) asm volatile("mbarrier.arrive.expect_tx.shared.b64 _, [%0], %1;" :: "r"(a), "r"((uint32_t)(n)) : "memory")
#define MBAR_WAIT(a, ph) do {                                                        \
    uint32_t _m = (a), _p = (ph), _d;                                                \
    asm volatile("{ .reg .pred p; mbarrier.try_wait.parity.acquire.cta.shared::cta.b64 p, [%1], %2; selp.b32 %0,1,0,p; }" \
                 : "=r"(_d) : "r"(_m), "r"(_p) : "memory");                          \
    if (!_d) {                                                                       \
        asm volatile("{ .reg .pred P1; W%=: mbarrier.try_wait.parity.acquire.cta.shared::cta.b64 P1, [%0], %1, 0x989680;" \
                     " @P1 bra.uni D%=; bra.uni W%=; D%=: }" :: "r"(_m), "r"(_p) : "memory"); \
    }                                                                                \
} while (0)

__device__ __forceinline__ void bulk_g2s(uint32_t dst, const void* src, uint32_t bytes, uint32_t mbar) {
    asm volatile("cp.async.bulk.shared::cluster.global.mbarrier::complete_tx::bytes [%0], [%1], %2, [%3];"
        :: "r"(dst), "l"(src), "r"(bytes), "r"(mbar) : "memory");
}

#define LDSM4(r, addr) \
    asm volatile("ldmatrix.sync.aligned.m8n8.x4.shared.b16 {%0,%1,%2,%3}, [%4];" \
        : "=r"((r)[0]), "=r"((r)[1]), "=r"((r)[2]), "=r"((r)[3]) : "r"(addr))

#define MMA16816(c, a, bb0, bb1) \
    asm volatile("mma.sync.aligned.m16n8k16.row.col.f32.f16.f16.f32 " \
        "{%0,%1,%2,%3}, {%4,%5,%6,%7}, {%8,%9}, {%0,%1,%2,%3};" \
        : "+f"((c)[0]), "+f"((c)[1]), "+f"((c)[2]), "+f"((c)[3]) \
        : "r"((a)[0]), "r"((a)[1]), "r"((a)[2]), "r"((a)[3]), "r"(bb0), "r"(bb1))

// ============================================================
// Kernel A: build U column j; emit fp16 Whi slice images.
// ============================================================
__device__ __forceinline__ float2 cmul(float2 a, float2 b) {
    return make_float2(a.x * b.x - a.y * b.y, a.x * b.y + a.y * b.x);
}
__device__ __forceinline__ float2 cadd(float2 a, float2 b) {
    return make_float2(a.x + b.x, a.y + b.y);
}

__global__ void build_U_kernel(const float* __restrict__ w) {
    __shared__ float2 st[DIM];
    const int j = blockIdx.x;
    const int t = threadIdx.x;  // 0..127

    st[t]       = make_float2(t == j ? 1.f : 0.f, 0.f);
    st[t + 128] = make_float2((t + 128) == j ? 1.f : 0.f, 0.f);
    __syncthreads();

    for (int l = 0; l < 6; ++l) {
        const int r = l % (NQ - 1) + 1;
        for (int q = 0; q < NQ; ++q) {
            const float phi = w[(l * NQ + q) * 3 + 0];
            const float th  = w[(l * NQ + q) * 3 + 1];
            const float om  = w[(l * NQ + q) * 3 + 2];
            const float ct = cosf(0.5f * th), sth = sinf(0.5f * th);
            const float a  = 0.5f * (phi + om), bb = 0.5f * (phi - om);
            const float ca = cosf(a),  sa = sinf(a);
            const float cb = cosf(bb), sb = sinf(bb);
            const float2 u00 = make_float2( ca * ct, -sa * ct);
            const float2 u01 = make_float2(-cb * sth, -sb * sth);
            const float2 u10 = make_float2( cb * sth, -sb * sth);
            const float2 u11 = make_float2( ca * ct,  sa * ct);

            const int b    = 7 - q;
            const int mask = 1 << b;
            const int low  = t & (mask - 1);
            const int k0   = ((t >> b) << (b + 1)) | low;
            const int k1   = k0 | mask;
            const float2 a0 = st[k0], a1 = st[k1];
            st[k0] = cadd(cmul(u00, a0), cmul(u01, a1));
            st[k1] = cadd(cmul(u10, a0), cmul(u11, a1));
            __syncthreads();
        }
        for (int q = 0; q < NQ; ++q) {
            const int tq = (q + r) % NQ;
            const int cb = 7 - q;
            const int tb = 7 - tq;
            if (t < 64) {
                const int plo = cb < tb ? cb : tb;
                const int phi_ = cb < tb ? tb : cb;
                const int low  = t & ((1 << plo) - 1);
                const int mid  = (t >> plo) & ((1 << (phi_ - plo - 1)) - 1);
                const int high = t >> (phi_ - 1);
                const int k0   = low | (mid << (plo + 1)) | (high << (phi_ + 1));
                const int k    = k0 | (1 << cb);
                const int p    = k  | (1 << tb);
                const float2 tmp = st[k];
                st[k] = st[p];
                st[p] = tmp;
            }
            __syncthreads();
        }
    }

    // Emit Whi slice images for this j (st[k] = U[k][j]).
    //   even popc(j): (w0,w1) = ( Re,  Im);  odd: (w0,w1) = ( Im, -Re)
    const bool odd = (__popc(j) & 1) != 0;
    const int jblock = j >> 6;
    const int koff = (j & 63) * 2;
#pragma unroll
    for (int h = 0; h < 2; ++h) {
        const int kst = t + h * 128;
        const float2 u = st[kst];
        const float W0 = odd ?  u.y : u.x;
        const float W1 = odd ? -u.x : u.y;
#pragma unroll
        for (int comp = 0; comp < 2; ++comp) {
            const float val = comp ? W1 : W0;
            const __half hi = __float2half_rn(val);
            const int c = 2 * kst + comp;
            const int chunk = c >> 7, n = c & 127;   // 128 cols per chunk
            const size_t gs = (size_t)(chunk * CSLICES + jblock);
            *(__half*)(d_B + (gs * BROWS + n) * BSTRIDE + koff) = hi;
        }
    }
}

// ============================================================
// Kernel B: y-build -> fp16 mma.sync GEMM -> z
// 256 threads = 8 warps (4 M x 2 N), warp tile 32x64.
// Each B slice is used twice (A=yhi, then A=ylo) before release:
// psi ~= yhi*Whi + ylo*Whi  (yhi*Wlo term dropped, ~1e-5 error).
// ============================================================
__global__ void __launch_bounds__(256, 1) sim_kernel(const float* __restrict__ inp,
                                                     float* __restrict__ out) {
    extern __shared__ __align__(1024) unsigned char smem[];
    const uint32_t sb = smem_u32(smem);
    const uint32_t Ab = sb;
    const uint32_t Bb = sb + ABYTES;
    const uint32_t MB = sb + ABYTES + 2 * BSLICE;
    const int tid = threadIdx.x;
    const int lane = tid & 31, warp = tid >> 5;
    const int wm = warp & 3, wn = warp >> 2;
    const int b0 = blockIdx.x * MT;

    if (tid == 0) { MBAR_INIT(MB, 1); MBAR_INIT(MB + 8, 1); }
    __syncthreads();
    if (tid == 0) {
        MBAR_EXPECT(MB, BSLICE);     bulk_g2s(Bb,          d_B,          BSLICE, MB);
        MBAR_EXPECT(MB + 8, BSLICE); bulk_g2s(Bb + BSLICE, d_B + BSLICE, BSLICE, MB + 8);
    }

    // ---- A build: y hi (k 0-255) and lo (k 256-511), fp16; 2 threads/row ----
    {
        const int row = tid >> 1, h = tid & 1;
        const float4 x0 = *(const float4*)(inp + (size_t)(b0 + row) * 8);
        const float4 x1 = *(const float4*)(inp + (size_t)(b0 + row) * 8 + 4);
        const float xs[8] = {x0.x, x0.y, x0.z, x0.w, x1.x, x1.y, x1.z, x1.w};
        float fc[8], fs[8];
#pragma unroll
        for (int q = 0; q < 8; ++q) sincosf(0.5f * xs[q], &fs[q], &fc[q]);
        float ph[16], pl[16];
#pragma unroll
        for (int i = 0; i < 16; ++i) {
            ph[i] = ((i & 8) ? fs[0] : fc[0]) * ((i & 4) ? fs[1] : fc[1]) *
                    ((i & 2) ? fs[2] : fc[2]) * ((i & 1) ? fs[3] : fc[3]);
            pl[i] = ((i & 8) ? fs[4] : fc[4]) * ((i & 4) ? fs[5] : fc[5]) *
                    ((i & 2) ? fs[6] : fc[6]) * ((i & 1) ? fs[7] : fc[7]);
        }
        unsigned char* arow = smem + (size_t)row * ASTRIDE;
#pragma unroll 4
        for (int j2 = 0; j2 < 128; j2 += 2) {
            const int jj = h * 128 + j2;
            float y0 = ph[jj >> 4] * pl[jj & 15];
            float y1 = ph[(jj + 1) >> 4] * pl[(jj + 1) & 15];
            if ((__popc(jj) & 3) >= 2)       y0 = -y0;
            if ((__popc(jj + 1) & 3) >= 2)   y1 = -y1;
            const __half h0 = __float2half_rn(y0), h1 = __float2half_rn(y1);
            const __half l0 = __float2half_rn(y0 - __half2float(h0));
            const __half l1 = __float2half_rn(y1 - __half2float(h1));
            __half2 hp; hp.x = h0; hp.y = h1;
            __half2 lp; lp.x = l0; lp.y = l1;
            *(__half2*)(arow + jj * 2)       = hp;
            *(__half2*)(arow + 512 + jj * 2) = lp;
        }
    }
    __syncthreads();

    // invariant per-lane ldmatrix offsets
    const uint32_t aoff = (uint32_t)((wm * 32 + (lane & 7) + ((lane >> 3) & 1) * 8) * ASTRIDE)
                        + ((lane >> 4) & 1) * 16;
    const uint32_t boff = (uint32_t)((wn * 64 + (lane & 7) + ((lane >> 4) & 1) * 8) * BSTRIDE)
                        + ((lane >> 3) & 1) * 16;

    float z[4][8];
#pragma unroll
    for (int zr = 0; zr < 4; ++zr)
#pragma unroll
        for (int i = 0; i < 8; ++i) z[zr][i] = 0.f;

    int gs = 0;
    for (int chunk = 0; chunk < NCHUNK; ++chunk) {
        float acc[2][8][4];
#pragma unroll
        for (int mf = 0; mf < 2; ++mf)
#pragma unroll
            for (int nf = 0; nf < 8; ++nf)
#pragma unroll
                for (int c = 0; c < 4; ++c) acc[mf][nf][c] = 0.f;

#pragma unroll 1
        for (int s = 0; s < CSLICES; ++s, ++gs) {
            const uint32_t bar = MB + (uint32_t)(gs & 1) * 8;
            MBAR_WAIT(bar, (gs >> 1) & 1);
            const uint32_t bbase = Bb + (uint32_t)(gs & 1) * BSLICE + boff;
            const uint32_t abase = Ab + aoff + (uint32_t)s * 128u;   // yhi k-window
#pragma unroll
            for (int t4 = 0; t4 < 4; ++t4) {
                uint32_t br[4][4];
#pragma unroll
                for (int nb = 0; nb < 4; ++nb)
                    LDSM4(br[nb], bbase + (uint32_t)nb * (16u * BSTRIDE) + (uint32_t)t4 * 32u);
                // pass 1: A = yhi
                {
                    uint32_t a[2][4];
#pragma unroll
                    for (int mf = 0; mf < 2; ++mf)
                        LDSM4(a[mf], abase + (uint32_t)mf * (16u * ASTRIDE) + (uint32_t)t4 * 32u);
#pragma unroll
                    for (int mf = 0; mf < 2; ++mf)
#pragma unroll
                        for (int nf = 0; nf < 8; ++nf)
                            MMA16816(acc[mf][nf], a[mf], br[nf >> 1][(nf & 1) * 2],
                                     br[nf >> 1][(nf & 1) * 2 + 1]);
                }
                // pass 2: A = ylo (k + 256 elements = +512 bytes)
                {
                    uint32_t a[2][4];
#pragma unroll
                    for (int mf = 0; mf < 2; ++mf)
                        LDSM4(a[mf], abase + 512u + (uint32_t)mf * (16u * ASTRIDE) + (uint32_t)t4 * 32u);
#pragma unroll
                    for (int mf = 0; mf < 2; ++mf)
#pragma unroll
                        for (int nf = 0; nf < 8; ++nf)
                            MMA16816(acc[mf][nf], a[mf], br[nf >> 1][(nf & 1) * 2],
                                     br[nf >> 1][(nf & 1) * 2 + 1]);
                }
            }
            __syncthreads();
            if (tid == 0 && gs + 2 < GSLICES) {
                MBAR_EXPECT(bar, BSLICE);
                bulk_g2s(Bb + (uint32_t)(gs & 1) * BSLICE,
                         d_B + (size_t)(gs + 2) * BSLICE, BSLICE, bar);
            }
        }

        // chunk epilogue: p = Re^2 + Im^2 (in-lane), fold signs into z
#pragma unroll
        for (int nf = 0; nf < 8; ++nf) {
            const int kst = chunk * 64 + wn * 32 + nf * 4 + (lane & 3);
            float sg[8];
#pragma unroll
            for (int i = 0; i < 8; ++i)
                sg[i] = ((kst >> (7 - i)) & 1) ? -1.f : 1.f;
#pragma unroll
            for (int mf = 0; mf < 2; ++mf) {
                const float p0 = acc[mf][nf][0] * acc[mf][nf][0] + acc[mf][nf][1] * acc[mf][nf][1];
                const float p1 = acc[mf][nf][2] * acc[mf][nf][2] + acc[mf][nf][3] * acc[mf][nf][3];
#pragma unroll
                for (int i = 0; i < 8; ++i) {
                    z[mf * 2][i]     = fmaf(sg[i], p0, z[mf * 2][i]);
                    z[mf * 2 + 1][i] = fmaf(sg[i], p1, z[mf * 2 + 1][i]);
                }
            }
        }
    }

    // cross-warp reduction via smem (A region is dead after last slice)
    {
        float* zbuf = (float*)smem;
        const int base = (warp * 32 + lane) * 32;
#pragma unroll
        for (int zr = 0; zr < 4; ++zr)
#pragma unroll
            for (int i = 0; i < 8; ++i)
                zbuf[base + zr * 8 + i] = z[zr][i];
    }
    __syncthreads();
    {
        const float* zbuf = (const float*)smem;
        const int r = tid >> 1, ih = tid & 1;
        const int wmr = r >> 5, tt = r & 31;
        const int mf = tt >> 4, hh = (tt >> 3) & 1, lg = tt & 7;
        const int zr = mf * 2 + hh;
        float4 sum = make_float4(0.f, 0.f, 0.f, 0.f);
#pragma unroll
        for (int wnn = 0; wnn < 2; ++wnn)
#pragma unroll
            for (int q = 0; q < 4; ++q) {
                const float4 v = *(const float4*)&zbuf[((wnn * 4 + wmr) * 32 + (lg * 4 + q)) * 32
                                                       + zr * 8 + ih * 4];
                sum.x += v.x; sum.y += v.y; sum.z += v.z; sum.w += v.w;
            }
        *(float4*)(out + (size_t)(b0 + r) * 8 + ih * 4) = sum;
    }
}

// ============================================================
extern "C" void kernel_launch(void* const* d_in, const int* in_sizes, int n_in,
                              void* d_out, int out_size) {
    const float* inputs  = (const float*)d_in[0];  // (65536, 8) float32
    const float* weights = (const float*)d_in[1];  // (6, 8, 3) float32
    float* out = (float*)d_out;                    // (65536, 8) float32

    const int B = in_sizes[0] / NQ;

    static int configured = 0;
    if (!configured) {
        cudaFuncSetAttribute(sim_kernel, cudaFuncAttributeMaxDynamicSharedMemorySize, SMEM_TOTAL);
        configured = 1;
    }

    build_U_kernel<<<DIM, 128>>>(weights);
    sim_kernel<<<B / MT, 256, SMEM_TOTAL>>>(inputs, out);
}